// round 1
// baseline (speedup 1.0000x reference)
#include <cuda_runtime.h>

#define B_Q   2048
#define NOBS  2048
#define PP    15
#define GG    21
#define EE    64
#define NCOL  65536   /* D*D */
#define KK    36      /* PP + GG */

#define BM 128
#define BN 128

// Scratch: mixed coefficients, transposed [k][b] for coalesced GEMM tile loads.
__device__ float g_coef[KK * B_Q];

// ---------------------------------------------------------------------------
// Kernel 1: brute-force 1-NN + small alpha-matrix mixing.
// 16 blocks x 128 threads = 2048 threads, one query each.
// ---------------------------------------------------------------------------
__global__ __launch_bounds__(128) void nn_coef_kernel(
    const float* __restrict__ positions, const float* __restrict__ obs_pos,
    const float* __restrict__ poly_dic,  const float* __restrict__ graph_dic,
    const float* __restrict__ alpha_poly, const float* __restrict__ alpha_graph)
{
    __shared__ float2 sObs[NOBS];
    __shared__ float  sAp[PP * PP];
    __shared__ float  sAg[EE * GG];

    const int tid = threadIdx.x;
    for (int i = tid; i < NOBS; i += blockDim.x)
        sObs[i] = ((const float2*)obs_pos)[i];
    for (int i = tid; i < PP * PP; i += blockDim.x)
        sAp[i] = alpha_poly[i];
    for (int i = tid; i < EE * GG; i += blockDim.x)
        sAg[i] = alpha_graph[i];
    __syncthreads();

    const int b = blockIdx.x * blockDim.x + tid;
    const float px = positions[2 * b];
    const float py = positions[2 * b + 1];

    float best = 3.0e38f;
    int   bi   = 0;
#pragma unroll 8
    for (int j = 0; j < NOBS; j++) {
        const float dx = px - sObs[j].x;
        const float dy = py - sObs[j].y;
        const float d2 = dx * dx + dy * dy;
        if (d2 < best) { best = d2; bi = j; }   // strict '<' keeps first min (matches jnp.argmin)
    }

    // poly: coef[p] = sum_q poly_dic[bi,q] * alpha_poly[q,p]
    float pdv[PP];
    const float* pd = poly_dic + bi * PP;
#pragma unroll
    for (int q = 0; q < PP; q++) pdv[q] = pd[q];
#pragma unroll
    for (int p = 0; p < PP; p++) {
        float s = 0.f;
#pragma unroll
        for (int q = 0; q < PP; q++) s = fmaf(pdv[q], sAp[q * PP + p], s);
        g_coef[p * B_Q + b] = s;
    }

    // graph: coef[15+g] = sum_e graph_dic[bi,e] * alpha_graph[e,g]
    float gdv[EE];
    const float* gd = graph_dic + bi * EE;
#pragma unroll
    for (int e = 0; e < EE; e++) gdv[e] = gd[e];
#pragma unroll 3
    for (int g = 0; g < GG; g++) {
        float s = 0.f;
#pragma unroll
        for (int e = 0; e < EE; e++) s = fmaf(gdv[e], sAg[e * GG + g], s);
        g_coef[(PP + g) * B_Q + b] = s;
    }
}

// ---------------------------------------------------------------------------
// Kernel 2: out[b,c] = sum_k coef[k,b] * S[k,c]   (M=2048, N=65536, K=36)
// 128x128 CTA tile, 256 threads, 8x8 per thread, inner product in fma.rn.f32x2.
// ---------------------------------------------------------------------------
__device__ __forceinline__ unsigned long long pack2(float lo, float hi) {
    unsigned long long r;
    asm("mov.b64 %0, {%1, %2};" : "=l"(r) : "f"(lo), "f"(hi));
    return r;
}
__device__ __forceinline__ void ffma2(unsigned long long& d,
                                      unsigned long long a,
                                      unsigned long long b) {
    asm("fma.rn.f32x2 %0, %1, %2, %0;" : "+l"(d) : "l"(a), "l"(b));
}

__global__ __launch_bounds__(256, 2) void opd_kernel(
    const float* __restrict__ S_poly, const float* __restrict__ S_graph,
    float* __restrict__ out)
{
    __shared__ float sA[KK][BM];   // coef tile  [k][row]
    __shared__ float sS[KK][BN];   // S tile     [k][col]

    const int tid     = threadIdx.x;
    const int rowTile = blockIdx.x;   // fast-varying: 16 CTAs share one S tile back-to-back
    const int colTile = blockIdx.y;

    // Load coef tile: 36 rows of 128 contiguous floats (g_coef is [k][b]).
#pragma unroll
    for (int i = tid; i < KK * BM; i += 256) {
        const int k = i >> 7, r = i & 127;
        sA[k][r] = g_coef[k * B_Q + rowTile * BM + r];
    }
    // Load S tile: row k from S_poly (k<15) or S_graph (k>=15).
#pragma unroll
    for (int i = tid; i < KK * BN; i += 256) {
        const int k = i >> 7, c = i & 127;
        const float* src = (k < PP) ? (S_poly + (size_t)k * NCOL)
                                    : (S_graph + (size_t)(k - PP) * NCOL);
        sS[k][c] = src[colTile * BN + c];
    }
    __syncthreads();

    const int tx = tid & 15;    // col group
    const int ty = tid >> 4;    // row group

    unsigned long long acc[8][4];
#pragma unroll
    for (int i = 0; i < 8; i++)
#pragma unroll
        for (int j = 0; j < 4; j++) acc[i][j] = 0ULL;

#pragma unroll
    for (int k = 0; k < KK; k++) {
        const float4 a03 = *(const float4*)&sA[k][ty * 8];
        const float4 a47 = *(const float4*)&sA[k][ty * 8 + 4];
        const ulonglong2 s01 = *(const ulonglong2*)&sS[k][tx * 8];
        const ulonglong2 s23 = *(const ulonglong2*)&sS[k][tx * 8 + 4];

        unsigned long long av[8];
        av[0] = pack2(a03.x, a03.x);
        av[1] = pack2(a03.y, a03.y);
        av[2] = pack2(a03.z, a03.z);
        av[3] = pack2(a03.w, a03.w);
        av[4] = pack2(a47.x, a47.x);
        av[5] = pack2(a47.y, a47.y);
        av[6] = pack2(a47.z, a47.z);
        av[7] = pack2(a47.w, a47.w);

#pragma unroll
        for (int i = 0; i < 8; i++) {
            ffma2(acc[i][0], av[i], s01.x);
            ffma2(acc[i][1], av[i], s01.y);
            ffma2(acc[i][2], av[i], s23.x);
            ffma2(acc[i][3], av[i], s23.y);
        }
    }

    const int rowBase = rowTile * BM + ty * 8;
    const int colBase = colTile * BN + tx * 8;
#pragma unroll
    for (int i = 0; i < 8; i++) {
        unsigned long long* op =
            (unsigned long long*)(out + (size_t)(rowBase + i) * NCOL + colBase);
        ((ulonglong2*)op)[0] = make_ulonglong2(acc[i][0], acc[i][1]);
        ((ulonglong2*)op)[1] = make_ulonglong2(acc[i][2], acc[i][3]);
    }
}

// ---------------------------------------------------------------------------
extern "C" void kernel_launch(void* const* d_in, const int* in_sizes, int n_in,
                              void* d_out, int out_size)
{
    const float* positions   = (const float*)d_in[0];
    const float* obs_pos     = (const float*)d_in[1];
    const float* poly_dic    = (const float*)d_in[2];
    const float* graph_dic   = (const float*)d_in[3];
    const float* alpha_poly  = (const float*)d_in[4];
    const float* alpha_graph = (const float*)d_in[5];
    const float* S_poly      = (const float*)d_in[6];
    const float* S_graph     = (const float*)d_in[7];
    float* out = (float*)d_out;

    nn_coef_kernel<<<B_Q / 128, 128>>>(positions, obs_pos, poly_dic, graph_dic,
                                       alpha_poly, alpha_graph);

    dim3 grid(B_Q / BM, NCOL / BN);   // (16, 512): row-tile fast => S-tile reuse in L2
    opd_kernel<<<grid, 256>>>(S_poly, S_graph, out);
}

// round 3
// speedup vs baseline: 1.7414x; 1.7414x over previous
#include <cuda_runtime.h>
#include <cstdint>

#define B_Q    2048
#define NOBS   2048
#define PP     15
#define GG     21
#define EE     64
#define NCOL   65536          /* D*D */
#define KK     36
#define KPAD   40             /* K padded to 5 k-steps of 8 */

#define BM 128                /* batch rows per CTA (MMA M) */
#define BN 128                /* S columns per CTA  (MMA N) */

// coef scratch: [b][KPAD] (tf32-rounded), cols 36..39 zero
__device__ float g_coef[B_Q * KPAD];

__device__ __forceinline__ uint32_t f2tf32(float x) {
    uint32_t u;
    asm("cvt.rna.tf32.f32 %0, %1;" : "=r"(u) : "f"(x));
    return u;
}

__device__ __forceinline__ void mma_tf32(float* d, const uint32_t* a, const uint32_t* b) {
    asm volatile(
        "mma.sync.aligned.m16n8k8.row.col.f32.tf32.tf32.f32 "
        "{%0,%1,%2,%3}, {%4,%5,%6,%7}, {%8,%9}, {%0,%1,%2,%3};"
        : "+f"(d[0]), "+f"(d[1]), "+f"(d[2]), "+f"(d[3])
        : "r"(a[0]), "r"(a[1]), "r"(a[2]), "r"(a[3]), "r"(b[0]), "r"(b[1]));
}

// ---------------------------------------------------------------------------
// Kernel 1: warp-per-query 1-NN + alpha mixing -> g_coef[b][KPAD] (tf32-rounded)
// ---------------------------------------------------------------------------
__global__ __launch_bounds__(256) void nn_coef_kernel(
    const float* __restrict__ positions, const float* __restrict__ obs_pos,
    const float* __restrict__ poly_dic,  const float* __restrict__ graph_dic,
    const float* __restrict__ alpha_poly, const float* __restrict__ alpha_graph)
{
    __shared__ float2 sObs[NOBS];
    __shared__ float  sAp[PP * PP];
    __shared__ float  sAg[EE * GG];

    const int tid = threadIdx.x;
    for (int i = tid; i < NOBS; i += 256) sObs[i] = ((const float2*)obs_pos)[i];
    for (int i = tid; i < PP * PP; i += 256) sAp[i] = alpha_poly[i];
    for (int i = tid; i < EE * GG; i += 256) sAg[i] = alpha_graph[i];
    __syncthreads();

    const int wid = tid >> 5, lid = tid & 31;
    const int b = blockIdx.x * 8 + wid;          // 256 blocks x 8 warps = 2048 queries
    const float px = positions[2 * b];
    const float py = positions[2 * b + 1];

    float bestD = 3.0e38f; int bestJ = 0;
    for (int j = lid; j < NOBS; j += 32) {
        const float dx = px - sObs[j].x;
        const float dy = py - sObs[j].y;
        const float d2 = dx * dx + dy * dy;
        if (d2 < bestD) { bestD = d2; bestJ = j; }
    }
    // exact argmin, first-index tiebreak: pack (d2bits, idx), min-reduce
    unsigned long long key = ((unsigned long long)__float_as_uint(bestD) << 32) | (unsigned)bestJ;
#pragma unroll
    for (int off = 16; off >= 1; off >>= 1) {
        unsigned long long o = __shfl_xor_sync(0xFFFFFFFFu, key, off);
        if (o < key) key = o;
    }
    const int bi = (int)(key & 0xFFFFFFFFu);

    const float* pd = poly_dic + bi * PP;
    const float* gd = graph_dic + bi * EE;
#pragma unroll
    for (int c = lid; c < KPAD; c += 32) {
        float s = 0.f;
        if (c < PP) {
#pragma unroll
            for (int q = 0; q < PP; q++) s = fmaf(pd[q], sAp[q * PP + c], s);
        } else if (c < KK) {
            const int g = c - PP;
#pragma unroll
            for (int e = 0; e < EE; e++) s = fmaf(gd[e], sAg[e * GG + g], s);
        }
        g_coef[b * KPAD + c] = __uint_as_float(f2tf32(s));
    }
}

// ---------------------------------------------------------------------------
// Kernel 2: out[b][c] = sum_k coef[b][k] * S[k][c]   via mma.sync tf32.
//   M = batch rows (128/CTA), N = S columns (128/CTA), K = 40.
//   8 warps, each computes a 32(M) x 64(N) sub-tile = 2x8 m16n8k8 frags / k-step.
// ---------------------------------------------------------------------------
#define SA_STRIDE 44          /* conflict-free for A-frag reads */
#define SS_STRIDE 136         /* conflict-free for B-frag reads */

__global__ __launch_bounds__(256, 2) void opd_kernel(
    const float* __restrict__ S_poly, const float* __restrict__ S_graph,
    float* __restrict__ out)
{
    __shared__ float sA[BM][SA_STRIDE];       // coef tile  [row][k]
    __shared__ float sS[KPAD][SS_STRIDE];     // S tile     [k][col]

    const int tid = threadIdx.x;
    const int wid = tid >> 5, lid = tid & 31;
    const int gr  = lid >> 2;                 // lane/4
    const int tg  = lid & 3;                  // lane%4
    const int wm  = wid >> 1;                 // 0..3 -> M offset 32*wm
    const int wn  = wid & 1;                  // 0..1 -> N offset 64*wn

    const int rowBase = blockIdx.x * BM;      // batch rows
    const int colBase = blockIdx.y * BN;      // S columns

    // ---- load coef tile (tf32-rounded already): 128 rows x 40 floats, float4
#pragma unroll
    for (int i = tid; i < BM * (KPAD / 4); i += 256) {
        const int r = i / (KPAD / 4), q = i % (KPAD / 4);
        const float4 v = *(const float4*)&g_coef[(rowBase + r) * KPAD + q * 4];
        *(float4*)&sA[r][q * 4] = v;
    }
    // ---- load S tile: rows k<36 from S_poly/S_graph, 36..39 zero; tf32-round
#pragma unroll
    for (int i = tid; i < KPAD * BN; i += 256) {
        const int k = i >> 7, c = i & 127;
        float v = 0.f;
        if (k < KK) {
            const float* src = (k < PP) ? (S_poly + (size_t)k * NCOL)
                                        : (S_graph + (size_t)(k - PP) * NCOL);
            v = src[colBase + c];
        }
        sS[k][c] = __uint_as_float(f2tf32(v));
    }
    __syncthreads();

    float d[2][8][4];
#pragma unroll
    for (int mt = 0; mt < 2; mt++)
#pragma unroll
        for (int f = 0; f < 8; f++)
#pragma unroll
            for (int j = 0; j < 4; j++) d[mt][f][j] = 0.f;

#pragma unroll
    for (int ks = 0; ks < KPAD / 8; ks++) {
        const int k0 = ks * 8;
        uint32_t a[2][4], bfr[8][2];
#pragma unroll
        for (int mt = 0; mt < 2; mt++) {
            const int r0 = wm * 32 + mt * 16 + gr;
            a[mt][0] = __float_as_uint(sA[r0][k0 + tg]);
            a[mt][1] = __float_as_uint(sA[r0 + 8][k0 + tg]);
            a[mt][2] = __float_as_uint(sA[r0][k0 + tg + 4]);
            a[mt][3] = __float_as_uint(sA[r0 + 8][k0 + tg + 4]);
        }
#pragma unroll
        for (int f = 0; f < 8; f++) {
            const int c0 = wn * 64 + f * 8 + gr;
            bfr[f][0] = __float_as_uint(sS[k0 + tg][c0]);
            bfr[f][1] = __float_as_uint(sS[k0 + tg + 4][c0]);
        }
#pragma unroll
        for (int mt = 0; mt < 2; mt++)
#pragma unroll
            for (int f = 0; f < 8; f++)
                mma_tf32(d[mt][f], a[mt], bfr[f]);
    }

    // ---- epilogue: c0,c1 -> (row, col..col+1); c2,c3 -> (row+8, ...)
#pragma unroll
    for (int mt = 0; mt < 2; mt++) {
        const int row0 = rowBase + wm * 32 + mt * 16 + gr;
#pragma unroll
        for (int f = 0; f < 8; f++) {
            const int col = colBase + wn * 64 + f * 8 + tg * 2;
            *(float2*)&out[(size_t)row0 * NCOL + col] =
                make_float2(d[mt][f][0], d[mt][f][1]);
            *(float2*)&out[(size_t)(row0 + 8) * NCOL + col] =
                make_float2(d[mt][f][2], d[mt][f][3]);
        }
    }
}

// ---------------------------------------------------------------------------
extern "C" void kernel_launch(void* const* d_in, const int* in_sizes, int n_in,
                              void* d_out, int out_size)
{
    const float* positions   = (const float*)d_in[0];
    const float* obs_pos     = (const float*)d_in[1];
    const float* poly_dic    = (const float*)d_in[2];
    const float* graph_dic   = (const float*)d_in[3];
    const float* alpha_poly  = (const float*)d_in[4];
    const float* alpha_graph = (const float*)d_in[5];
    const float* S_poly      = (const float*)d_in[6];
    const float* S_graph     = (const float*)d_in[7];
    float* out = (float*)d_out;

    nn_coef_kernel<<<B_Q / 8, 256>>>(positions, obs_pos, poly_dic, graph_dic,
                                     alpha_poly, alpha_graph);

    // grid.x = batch tiles (fast) so 16 CTAs sharing one S tile run adjacently
    dim3 grid(B_Q / BM, NCOL / BN);   // (16, 512)
    opd_kernel<<<grid, 256>>>(S_poly, S_graph, out);
}